// round 10
// baseline (speedup 1.0000x reference)
#include <cuda_runtime.h>
#include <cstdint>
#include <cmath>

#define ND    1000
#define FIN   2048
#define DD    128
#define SK    8
#define TMAXP 150016

// ---------------- device scratch ----------------
__device__ __align__(16) float g_h1[ND * DD];
__device__ __align__(16) float g_h [ND * DD];
__device__ __align__(16) float g_agg[ND * DD];
__device__ float g_cnt[ND];
__device__ __align__(16) float g_fx[ND * DD];       // finalX fp32
__device__ __align__(16) float g_U [256 * 512];     // U = oW1 @ oW2sel  [k=256][s=512]
__device__ __align__(16) float g_R [ND * 512];      // R = fx @ U[0:128] + c
__device__ __align__(16) float g_S [ND * 512];      // S = fx @ U[128:256]
__device__ __align__(16) float g_c [512];           // c = oB1 @ oW2sel + oB2sel
// counting sort of tpl rows by first drug index
__device__ int g_bin [1024];
__device__ int g_bofs[1025];
__device__ int g_bcur[1024];
__device__ int g_pt[TMAXP];
__device__ int g_pj[TMAXP];

// ---------------- K0: zero scratch ----------------
__global__ void k_zero() {
    int i = blockIdx.x * 256 + threadIdx.x;
    if (i < ND * DD) { g_h1[i] = 0.0f; g_agg[i] = 0.0f; }
    if (i < ND) g_cnt[i] = 0.0f;
    if (i < 1024) g_bin[i] = 0;
}

// ---------------- sort pass 1: histogram of tpl[:,0] ----------------
__global__ void k_hist(const int* __restrict__ tpl, int T) {
    int t = blockIdx.x * 256 + threadIdx.x;
    if (t < T) atomicAdd(&g_bin[tpl[2 * t]], 1);
}

// ---------------- sort pass 2: exclusive scan (1 block) ----------------
__global__ void k_scan() {
    __shared__ int s[1024];
    int t = threadIdx.x;
    int v = g_bin[t];
    s[t] = v;
    __syncthreads();
    for (int off = 1; off < 1024; off <<= 1) {
        int u = (t >= off) ? s[t - off] : 0;
        __syncthreads();
        s[t] += u;
        __syncthreads();
    }
    int excl = s[t] - v;
    g_bofs[t] = excl;
    g_bcur[t] = excl;
    if (t == 1023) g_bofs[1024] = s[t];
}

// ---------------- sort pass 3: scatter ----------------
__global__ void k_scat(const int* __restrict__ tpl, int T) {
    int t = blockIdx.x * 256 + threadIdx.x;
    if (t < T) {
        int2 p = ((const int2*)tpl)[t];
        int pos = atomicAdd(&g_bcur[p.x], 1);
        g_pt[pos] = t;
        g_pj[pos] = p.y;
    }
}

// ---------------- K1: h1 = drugF @ W1 (split-K, atomic) ----------------
__global__ void k_mlp1(const float* __restrict__ dF, const float* __restrict__ W1) {
    __shared__ float As[16][33];
    __shared__ float Bs[32][128];
    const int rb = blockIdx.x * 16;
    const int k0 = blockIdx.y * (FIN / SK);
    const int t  = threadIdx.x;
    const int c  = t & 127, rg = t >> 7;
    float acc[8];
#pragma unroll
    for (int r = 0; r < 8; r++) acc[r] = 0.0f;
    for (int kb = 0; kb < FIN / SK; kb += 32) {
        {
            int kk = t & 31, r = t >> 5;
#pragma unroll
            for (int i = 0; i < 2; i++) {
                int rr = r + i * 8, grow = rb + rr;
                As[rr][kk] = (grow < ND) ? dF[(size_t)grow * FIN + k0 + kb + kk] : 0.0f;
            }
        }
#pragma unroll
        for (int i = 0; i < 16; i++) {
            int lin = t + i * 256, kk = lin >> 7, cc = lin & 127;
            Bs[kk][cc] = W1[(size_t)(k0 + kb + kk) * DD + cc];
        }
        __syncthreads();
#pragma unroll 8
        for (int kk = 0; kk < 32; kk++) {
            float b = Bs[kk][c];
#pragma unroll
            for (int rr = 0; rr < 8; rr++) acc[rr] += As[rg * 8 + rr][kk] * b;
        }
        __syncthreads();
    }
#pragma unroll
    for (int rr = 0; rr < 8; rr++) {
        int grow = rb + rg * 8 + rr;
        if (grow < ND) atomicAdd(&g_h1[grow * DD + c], acc[rr]);
    }
}

// ---------------- K2: h = relu(relu(h1+b1) @ W2 + b2) ----------------
__global__ void k_mlp2(const float* __restrict__ W2, const float* __restrict__ b1,
                       const float* __restrict__ b2) {
    __shared__ float hs[8][128];
    const int rb = blockIdx.x * 8;
    const int t  = threadIdx.x;
#pragma unroll
    for (int i = 0; i < 4; i++) {
        int lin = t + i * 256, r = lin >> 7, cc = lin & 127;
        hs[r][cc] = fmaxf(g_h1[(rb + r) * DD + cc] + b1[cc], 0.0f);
    }
    __syncthreads();
    const int c = t & 127, rg = t >> 7;
    float acc[4];
#pragma unroll
    for (int rr = 0; rr < 4; rr++) acc[rr] = b2[c];
#pragma unroll 4
    for (int k = 0; k < 128; k++) {
        float w = W2[k * DD + c];
#pragma unroll
        for (int rr = 0; rr < 4; rr++) acc[rr] += hs[rg * 4 + rr][k] * w;
    }
#pragma unroll
    for (int rr = 0; rr < 4; rr++)
        g_h[(rb + rg * 4 + rr) * DD + c] = fmaxf(acc[rr], 0.0f);
}

// ---------------- K3: edge aggregation (only dst < ND matters) ----------------
__global__ void k_agg(const int* __restrict__ ei, const float* __restrict__ pe, int E) {
    const int e = blockIdx.x * 256 + threadIdx.x;
    const int lane = threadIdx.x & 31;
    int dst = 0, src = 0;
    bool act = false;
    if (e < E) {
        dst = ei[E + e];
        act = (dst < ND);
        if (act) src = ei[e];
    }
    unsigned m = __ballot_sync(0xffffffffu, act);
    while (m) {
        int leader = __ffs(m) - 1;
        m &= m - 1;
        int d = __shfl_sync(0xffffffffu, dst, leader);
        int s = __shfl_sync(0xffffffffu, src, leader);
        const float4* p = (s < ND) ? (const float4*)(g_h + s * DD)
                                   : (const float4*)(pe + (size_t)(s - ND) * DD);
        float4 v = p[lane];
        float* ap = g_agg + d * DD + lane * 4;
        asm volatile("red.global.add.v4.f32 [%0], {%1,%2,%3,%4};"
                     :: "l"(ap), "f"(v.x), "f"(v.y), "f"(v.z), "f"(v.w) : "memory");
        if (lane == 0) atomicAdd(&g_cnt[d], 1.0f);
    }
}

// ---------------- K4: finalX = relu(mean @ Wl + bl + h @ Wr), fp32 ----------
__global__ void k_sage(const float* __restrict__ Wl, const float* __restrict__ bl,
                       const float* __restrict__ Wr) {
    __shared__ float ms[8][128];
    __shared__ float hs[8][128];
    const int rb = blockIdx.x * 8;
    const int t  = threadIdx.x;
#pragma unroll
    for (int i = 0; i < 4; i++) {
        int lin = t + i * 256, r = lin >> 7, cc = lin & 127;
        float cnt = fmaxf(g_cnt[rb + r], 1.0f);
        ms[r][cc] = g_agg[(rb + r) * DD + cc] / cnt;
        hs[r][cc] = g_h[(rb + r) * DD + cc];
    }
    __syncthreads();
    const int c = t & 127, rg = t >> 7;
    float acc[4];
#pragma unroll
    for (int rr = 0; rr < 4; rr++) acc[rr] = bl[c];
#pragma unroll 4
    for (int k = 0; k < 128; k++) {
        float wl = Wl[k * DD + c];
        float wr = Wr[k * DD + c];
#pragma unroll
        for (int rr = 0; rr < 4; rr++)
            acc[rr] += ms[rg * 4 + rr][k] * wl + hs[rg * 4 + rr][k] * wr;
    }
#pragma unroll
    for (int rr = 0; rr < 4; rr++)
        g_fx[(rb + rg * 4 + rr) * DD + c] = fmaxf(acc[rr], 0.0f);
}

// ---------------- K5: U = oW1 @ oW2sel, + fold c = oB1 @ oW2sel + oB2sel -----
// grid (8, 4): M tiles of 32 (rows of oW1), N tiles of 128 (selected cols)
__global__ void k_u(const float* __restrict__ oW1, const float* __restrict__ oW2,
                    const float* __restrict__ oB1, const float* __restrict__ oB2,
                    const int* __restrict__ ses, int S, int nSe) {
    __shared__ float As[32][33];
    __shared__ float Bs[32][128];
    __shared__ int   sess[128];
    const int m0 = blockIdx.x * 32;
    const int n0 = blockIdx.y * 128;
    const int t  = threadIdx.x;
    if (t < 128) {
        int sn = n0 + t;
        sess[t] = (sn < S) ? ses[sn] : 0;
    }
    __syncthreads();
    const int c = t & 127, rg = t >> 7;
    float acc[16];
#pragma unroll
    for (int r = 0; r < 16; r++) acc[r] = 0.0f;
    float cacc = 0.0f;
    for (int kb = 0; kb < DD; kb += 32) {
#pragma unroll
        for (int i = 0; i < 4; i++) {
            int lin = t + i * 256, r = lin >> 5, kk = lin & 31;
            As[r][kk] = oW1[(size_t)(m0 + r) * DD + kb + kk];
        }
#pragma unroll
        for (int i = 0; i < 16; i++) {
            int lin = t + i * 256, kk = lin >> 7, cc = lin & 127;
            Bs[kk][cc] = oW2[(size_t)(kb + kk) * nSe + sess[cc]];
        }
        __syncthreads();
        if (blockIdx.x == 0 && t < 128) {
#pragma unroll 8
            for (int kk = 0; kk < 32; kk++)
                cacc += oB1[kb + kk] * Bs[kk][t];
        }
#pragma unroll 8
        for (int kk = 0; kk < 32; kk++) {
            float b = Bs[kk][c];
#pragma unroll
            for (int rr = 0; rr < 16; rr++) acc[rr] += As[rg * 16 + rr][kk] * b;
        }
        __syncthreads();
    }
#pragma unroll
    for (int rr = 0; rr < 16; rr++)
        g_U[(size_t)(m0 + rg * 16 + rr) * 512 + n0 + c] = acc[rr];
    if (blockIdx.x == 0 && t < 128) {
        int sn = n0 + t;
        g_c[sn] = (sn < S) ? (cacc + oB2[sess[t]]) : 0.0f;
    }
}

// ---------------- K7: R = fx @ U[0:128] + c ;  S = fx @ U[128:256] -----------
// grid (16, 4, 2): M tiles 64 (fx rows), N tiles 128, z selects R/S
__global__ void k_rs() {
    __shared__ float As[64][33];
    __shared__ float Bs[32][128];
    const int m0 = blockIdx.x * 64;
    const int n0 = blockIdx.y * 128;
    const int z  = blockIdx.z;
    const int t  = threadIdx.x;
    const int c  = t & 127, rg = t >> 7;
    float acc[32];
#pragma unroll
    for (int r = 0; r < 32; r++) acc[r] = 0.0f;
    for (int kb = 0; kb < DD; kb += 32) {
#pragma unroll
        for (int i = 0; i < 8; i++) {
            int lin = t + i * 256, r = lin >> 5, kk = lin & 31;
            int row = m0 + r;
            As[r][kk] = (row < ND) ? g_fx[(size_t)row * DD + kb + kk] : 0.0f;
        }
#pragma unroll
        for (int i = 0; i < 16; i++) {
            int lin = t + i * 256, kk = lin >> 7, cc = lin & 127;
            Bs[kk][cc] = g_U[(size_t)(z * 128 + kb + kk) * 512 + n0 + cc];
        }
        __syncthreads();
#pragma unroll 8
        for (int kk = 0; kk < 32; kk++) {
            float b = Bs[kk][c];
#pragma unroll
            for (int rr = 0; rr < 32; rr++) acc[rr] += As[rg * 32 + rr][kk] * b;
        }
        __syncthreads();
    }
    float cadd = (z == 0) ? g_c[n0 + c] : 0.0f;
    float* dst = z ? g_S : g_R;
#pragma unroll
    for (int rr = 0; rr < 32; rr++) {
        int row = m0 + rg * 32 + rr;
        if (row < ND) dst[(size_t)row * 512 + n0 + c] = acc[rr] + cadd;
    }
}

// ---------------- K8: out rows grouped by i — R[i] cached in smem ------------
// one block per drug bin; each iteration handles 2 tpl rows (256 thr = 2 x 128)
__global__ void __launch_bounds__(256)
k_out3(float* __restrict__ out, int S) {
    __shared__ float Rs[512];
    const int b = blockIdx.x;
    const int start = g_bofs[b], end = g_bofs[b + 1];
    if (start == end) return;
    const int t = threadIdx.x;
    if (t < 128)
        ((float4*)Rs)[t] = ((const float4*)(g_R + (size_t)b * 512))[t];
    __syncthreads();
    const int c = t & 127, r2 = t >> 7;
    const int q = S >> 2;                 // 125 quads (S % 4 == 0)
    if (c >= q) return;
    const float4 rv = ((const float4*)Rs)[c];
    for (int r = start + r2; r < end; r += 2) {
        int row = g_pt[r], j = g_pj[r];
        float4 s4 = __ldg((const float4*)(g_S + (size_t)j * 512) + c);
        float4 o = { rv.x + s4.x, rv.y + s4.y, rv.z + s4.z, rv.w + s4.w };
        __stcs((float4*)(out + (size_t)row * S) + c, o);
    }
}

// ---------------- host ----------------
extern "C" void kernel_launch(void* const* d_in, const int* in_sizes, int n_in,
                              void* d_out, int out_size) {
    const float* drugF = (const float*)d_in[0];
    const int*   ei    = (const int*)d_in[1];
    const int*   tpl   = (const int*)d_in[2];
    const int*   ses   = (const int*)d_in[3];
    const float* W1    = (const float*)d_in[4];
    const float* b1    = (const float*)d_in[5];
    const float* W2    = (const float*)d_in[6];
    const float* b2    = (const float*)d_in[7];
    const float* pe    = (const float*)d_in[8];
    const float* Wl    = (const float*)d_in[9];
    const float* bl    = (const float*)d_in[10];
    const float* Wr    = (const float*)d_in[11];
    const float* oW1   = (const float*)d_in[12];
    const float* oB1   = (const float*)d_in[13];
    const float* oW2   = (const float*)d_in[14];
    const float* oB2   = (const float*)d_in[15];

    const int E   = in_sizes[1] / 2;
    const int T   = in_sizes[2] / 2;
    const int S   = in_sizes[3];
    const int nSe = in_sizes[15];
    float* out = (float*)d_out;

    k_zero <<<(ND * DD + 255) / 256, 256>>>();
    k_hist <<<(T + 255) / 256, 256>>>(tpl, T);
    k_scan <<<1, 1024>>>();
    k_scat <<<(T + 255) / 256, 256>>>(tpl, T);
    k_mlp1 <<<dim3((ND + 15) / 16, SK), 256>>>(drugF, W1);
    k_u    <<<dim3(8, 4), 256>>>(oW1, oW2, oB1, oB2, ses, S, nSe);
    k_mlp2 <<<ND / 8, 256>>>(W2, b1, b2);
    k_agg  <<<(E + 255) / 256, 256>>>(ei, pe, E);
    k_sage <<<ND / 8, 256>>>(Wl, bl, Wr);
    k_rs   <<<dim3(16, 4, 2), 256>>>();
    k_out3 <<<ND, 256>>>(out, S);
}